// round 15
// baseline (speedup 1.0000x reference)
#include <cuda_runtime.h>
#include <cuda_fp16.h>
#include <cstdint>

#define B_   4
#define T_   2048
#define C_   1024
#define H_   16
#define DH_  64
#define C3_  3072
#define M_   (B_*T_)      // 8192 rows
#define K_   1024

// ---------------------------------------------------------------------------
// Scratch (no cudaMalloc). g_xh reused for attention fp16 output (x dead by then).
// ---------------------------------------------------------------------------
__device__ __half g_xh[(size_t)M_ * C_];
__device__ __half g_qkvh[(size_t)M_ * C3_];   // Q,K,V (fp16, single)
__device__ __half g_wqh[(size_t)C3_ * C_];    // W_qkv^T fp16
__device__ __half g_woh[(size_t)C_ * C_];     // W_o^T fp16

// ---------------------------------------------------------------------------
__device__ __forceinline__ uint32_t smem_u32(const void* p) {
    uint32_t a;
    asm("{ .reg .u64 t; cvta.to.shared.u64 t, %1; cvt.u32.u64 %0, t; }" : "=r"(a) : "l"(p));
    return a;
}
__device__ __forceinline__ void cpa16(uint32_t dst, const void* src) {
    asm volatile("cp.async.cg.shared.global [%0], [%1], 16;" :: "r"(dst), "l"(src));
}
__device__ __forceinline__ void ldm4(uint32_t* r, uint32_t addr) {
    asm volatile("ldmatrix.sync.aligned.m8n8.x4.shared.b16 {%0,%1,%2,%3}, [%4];"
                 : "=r"(r[0]), "=r"(r[1]), "=r"(r[2]), "=r"(r[3]) : "r"(addr));
}
__device__ __forceinline__ void ldm4t(uint32_t* r, uint32_t addr) {
    asm volatile("ldmatrix.sync.aligned.m8n8.x4.trans.shared.b16 {%0,%1,%2,%3}, [%4];"
                 : "=r"(r[0]), "=r"(r[1]), "=r"(r[2]), "=r"(r[3]) : "r"(addr));
}
__device__ __forceinline__ void mma16816h(float* d, const uint32_t* a, const uint32_t* b) {
    asm volatile("mma.sync.aligned.m16n8k16.row.col.f32.f16.f16.f32 "
                 "{%0,%1,%2,%3}, {%4,%5,%6,%7}, {%8,%9}, {%0,%1,%2,%3};"
                 : "+f"(d[0]), "+f"(d[1]), "+f"(d[2]), "+f"(d[3])
                 : "r"(a[0]), "r"(a[1]), "r"(a[2]), "r"(a[3]), "r"(b[0]), "r"(b[1]));
}
__device__ __forceinline__ uint32_t pack_h2(float a, float b) {
    uint32_t r;
    asm("cvt.rn.f16x2.f32 %0, %1, %2;" : "=r"(r) : "f"(b), "f"(a));
    return r;
}

// ---------------------------------------------------------------------------
__global__ void to_h16(const float* __restrict__ x, __half* __restrict__ o, int n)
{
    int i = blockIdx.x * blockDim.x + threadIdx.x;
    if (i < n) o[i] = __float2half_rn(x[i]);
}

// Transpose: W[K][N] fp32 -> T[N][K] fp16
__global__ void transT_h16(const float* __restrict__ W,
                           __half* __restrict__ Th, int K, int N)
{
    __shared__ float t[32][33];
    int n0 = blockIdx.x * 32, k0 = blockIdx.y * 32;
    int tx = threadIdx.x, ty = threadIdx.y;
    for (int r = ty; r < 32; r += 8)
        t[r][tx] = W[(size_t)(k0 + r) * N + n0 + tx];
    __syncthreads();
    for (int r = ty; r < 32; r += 8)
        Th[(size_t)(n0 + r) * K + k0 + tx] = __float2half_rn(t[tx][r]);
}

// ---------------------------------------------------------------------------
// mma.sync fp16 GEMM:  C[M,N] = A[M,K] * B^T, single product.
// CTA 256x128, 8 warps as 4(M) x 2(N); warp tile 64x64 -> MMA:LDSM ratio 4.0
// (32 MMAs per 8 ldmatrix per k16-chunk). ~175 regs -> 1 CTA/SM.
// BK=32, 3-stage cp.async, XOR-swizzled smem.
// ---------------------------------------------------------------------------
#define BKSLAB     32
#define AOPBg      16384                // A: 256 rows x 32k x 2B
#define BOPBg      8192                 // B: 128 rows x 32k x 2B
#define STAGEB     (AOPBg + BOPBg)      // 24576
#define GSTAGES    3
#define GEMM_SMEM  (GSTAGES * STAGEB)   // 73728 B

__global__ void gemm_mma(
    const __half* __restrict__ Ah_, const __half* __restrict__ Bh_,
    float* __restrict__ Cf, __half* __restrict__ Chi, int N)
{
    extern __shared__ char smem[];
    const uint32_t sb = smem_u32(smem);
    const int tid  = threadIdx.x;
    const int m0   = blockIdx.y * 256;
    const int n0   = blockIdx.x * 128;
    const int wid  = tid >> 5, lane = tid & 31;
    const int warp_m = (wid & 3) * 64;
    const int warp_n = (wid >> 2) * 64;

    const __half* pA  = Ah_ + (size_t)m0 * K_;
    const __half* pBh = Bh_ + (size_t)n0 * K_;

    // per stage: A 1024 chunks + B 512 chunks (16B each) = 6 per thread
    auto load_stage = [&](int it, int slot) {
        const uint32_t st = sb + slot * STAGEB;
        const int kb = it * BKSLAB;
#pragma unroll
        for (int i = 0; i < 6; i++) {
            const __half* base = (i < 4) ? pA : pBh;
            int w   = (i < 4) ? (((i & 3) << 8) + tid) : (((i & 1) << 8) + tid);
            int row = w >> 2;                  // A: 0..255, B: 0..127
            int c   = w & 3;
            const void* src = base + (size_t)row * K_ + kb + c * 8;
            const int ngrp = (i < 4) ? 32 : 16;
            uint32_t dst = st + ((i < 4) ? 0u : (uint32_t)AOPBg)
                         + (uint32_t)(c * ngrp + (row >> 3)) * 128
                         + (((row & 7) ^ (c << 1)) * 16);
            cpa16(dst, src);
        }
        asm volatile("cp.async.commit_group;" ::: "memory");
    };

    float acc[4][8][4];
#pragma unroll
    for (int a = 0; a < 4; a++)
#pragma unroll
        for (int b = 0; b < 8; b++)
#pragma unroll
            for (int c = 0; c < 4; c++) acc[a][b][c] = 0.f;

    const int mA  = warp_m + (lane & 15);
    const int mA8 = mA >> 3, mA7 = mA & 7;
    const int k8A = lane >> 4;
    const int nB  = warp_n + ((lane >> 4) << 3) + (lane & 7);
    const int nB8 = nB >> 3, nB7 = nB & 7;
    const int k8B = (lane >> 3) & 1;

    load_stage(0, 0);
    load_stage(1, 1);

    const int NIT = K_ / BKSLAB;                  // 32
    for (int it = 0; it < NIT; it++) {
        if (it + 1 < NIT) asm volatile("cp.async.wait_group 1;" ::: "memory");
        else              asm volatile("cp.async.wait_group 0;" ::: "memory");
        __syncthreads();
        if (it + 2 < NIT) load_stage(it + 2, (it + 2) % GSTAGES);

        const uint32_t st = sb + (it % GSTAGES) * STAGEB;
        const uint32_t AH = st, BH = st + AOPBg;

#pragma unroll
        for (int ks = 0; ks < 2; ks++) {
            const int cA = ks * 2 + k8A;
            const int cB = ks * 2 + k8B;
            const uint32_t offA = (uint32_t)(cA * 32 + mA8) * 128 + ((mA7 ^ (cA << 1)) * 16);
            const uint32_t offB = (uint32_t)(cB * 16 + nB8) * 128 + ((nB7 ^ (cB << 1)) * 16);

            uint32_t ah[4][4], bb[8][2];
#pragma unroll
            for (int mt = 0; mt < 4; mt++)
                ldm4(ah[mt], AH + offA + mt * 256);
#pragma unroll
            for (int j = 0; j < 4; j++)
                ldm4(&bb[j * 2][0], BH + offB + j * 256);
#pragma unroll
            for (int mt = 0; mt < 4; mt++)
#pragma unroll
                for (int nt = 0; nt < 8; nt++)
                    mma16816h(acc[mt][nt], ah[mt], bb[nt]);
        }
    }

    const int r0 = m0 + warp_m + (lane >> 2);
    const int c0 = n0 + warp_n + (lane & 3) * 2;
    if (Chi) {
#pragma unroll
        for (int mt = 0; mt < 4; mt++) {
#pragma unroll
            for (int nt = 0; nt < 8; nt++) {
                size_t o0 = (size_t)(r0 + mt * 16) * N + c0 + nt * 8;
                size_t o1 = o0 + (size_t)8 * N;
                *(uint32_t*)(Chi + o0) = pack_h2(acc[mt][nt][0], acc[mt][nt][1]);
                *(uint32_t*)(Chi + o1) = pack_h2(acc[mt][nt][2], acc[mt][nt][3]);
            }
        }
    } else {
#pragma unroll
        for (int mt = 0; mt < 4; mt++) {
#pragma unroll
            for (int nt = 0; nt < 8; nt++) {
                float* p = Cf + (size_t)(r0 + mt * 16) * N + c0 + nt * 8;
                *(float2*)p                   = make_float2(acc[mt][nt][0], acc[mt][nt][1]);
                *(float2*)(p + (size_t)8 * N) = make_float2(acc[mt][nt][2], acc[mt][nt][3]);
            }
        }
    }
}

// ---------------------------------------------------------------------------
// fp16 flash attention, causal + ALiBi. All matmuls single product. (R12, unchanged)
// ---------------------------------------------------------------------------
#define AQT       128
#define AKT       64
#define AOPB      8192
#define ASTAGEB   (2 * AOPB)             // K, V
#define ATT_SMEM  (16384 + 2 * ASTAGEB)  // 49152 B

__global__ void __launch_bounds__(256, 2) attn_mma(
    const __half* __restrict__ qkv, __half* __restrict__ oh)
{
    extern __shared__ char smem[];
    const uint32_t sb = smem_u32(smem);
    const uint32_t Qs = sb;
    const uint32_t ST0 = sb + 16384;

    const int tid  = threadIdx.x;
    const int wid  = tid >> 5, lane = tid & 31;
    const int b    = blockIdx.z;
    const int h    = blockIdx.y;
    const int qt   = blockIdx.x;
    const int q0   = qt * AQT;
    const int nkt  = 2 * qt + 2;
    const size_t rbase = (size_t)b * T_;

    const float LOG2E = 1.4426950408889634f;
    const float sc2 = LOG2E / 32.0f;
    const float sl2 = exp2f(-0.5f * (float)(h + 1)) * LOG2E;

    for (int i = tid; i < 1024; i += 256) {
        int r = (i >> 3) & 127, c8 = i & 7;
        const void* src = qkv + (rbase + q0 + r) * C3_ + h * DH_ + c8 * 8;
        uint32_t dst = Qs + (c8 * 16 + (r >> 3)) * 128 + (((r & 7) ^ c8) * 16);
        cpa16(dst, src);
    }
    auto load_stage = [&](int kt, int slot) {
        const int k0 = kt * AKT;
        const uint32_t st = ST0 + slot * ASTAGEB;
        for (int i = tid; i < 1024; i += 256) {
            int op = i >> 9, r = (i >> 3) & 63, c8 = i & 7;
            int coloff = ((op == 0) ? C_ : 2 * C_) + h * DH_;
            const void* src = qkv + (rbase + k0 + r) * C3_ + coloff + c8 * 8;
            uint32_t dst = st + op * AOPB + (c8 * 8 + (r >> 3)) * 128 + (((r & 7) ^ c8) * 16);
            cpa16(dst, src);
        }
        asm volatile("cp.async.commit_group;" ::: "memory");
    };
    load_stage(0, 0);

    float oacc[8][4];
#pragma unroll
    for (int j = 0; j < 8; j++)
#pragma unroll
        for (int c = 0; c < 4; c++) oacc[j][c] = 0.f;
    float m0r = -1e30f, m1r = -1e30f, l0 = 0.f, l1 = 0.f;

    const int rA   = wid * 16 + (lane & 15);
    const int rA8  = rA >> 3, rA7 = rA & 7;
    const int qc8h = lane >> 4;
    const int nKl  = (lane & 7) + ((lane >> 4) << 3);
    const int kc8h = (lane >> 3) & 1;
    const int rVl  = (lane & 7) + (((lane >> 3) & 1) << 3);
    const int vc8h = lane >> 4;
    const int row0 = q0 + wid * 16 + (lane >> 2);
    const int row1 = row0 + 8;

    for (int kt = 0; kt < nkt; kt++) {
        asm volatile("cp.async.wait_group 0;" ::: "memory");
        __syncthreads();
        if (kt + 1 < nkt) load_stage(kt + 1, (kt + 1) & 1);

        const int k0 = kt * AKT;
        const uint32_t st = ST0 + (kt & 1) * ASTAGEB;
        const uint32_t Ks = st, Vs = st + AOPB;

        float sacc[8][4];
#pragma unroll
        for (int j = 0; j < 8; j++)
#pragma unroll
            for (int c = 0; c < 4; c++) sacc[j][c] = 0.f;

#pragma unroll
        for (int ks = 0; ks < 4; ks++) {
            const int cq = 2 * ks + qc8h;
            const int ck = 2 * ks + kc8h;
            uint32_t qf[4];
            const uint32_t qoff = (uint32_t)(cq * 16 + rA8) * 128 + ((rA7 ^ cq) * 16);
            ldm4(qf, Qs + qoff);
#pragma unroll
            for (int j = 0; j < 4; j++) {
                uint32_t kf[4];
                const int rowK = 16 * j + nKl;
                const uint32_t koff = (uint32_t)(ck * 8 + (rowK >> 3)) * 128
                                    + (((rowK & 7) ^ ck) * 16);
                ldm4(kf, Ks + koff);
                mma16816h(sacc[2 * j],     qf, kf);
                mma16816h(sacc[2 * j + 1], qf, kf + 2);
            }
        }

        float mx0 = -1e30f, mx1 = -1e30f;
#pragma unroll
        for (int j = 0; j < 8; j++) {
            int col = k0 + j * 8 + (lane & 3) * 2;
            float s0 = (col     <= row0) ? sacc[j][0] * sc2 + sl2 * (float)(col     - row0) : -1e30f;
            float s1 = (col + 1 <= row0) ? sacc[j][1] * sc2 + sl2 * (float)(col + 1 - row0) : -1e30f;
            float s2 = (col     <= row1) ? sacc[j][2] * sc2 + sl2 * (float)(col     - row1) : -1e30f;
            float s3 = (col + 1 <= row1) ? sacc[j][3] * sc2 + sl2 * (float)(col + 1 - row1) : -1e30f;
            sacc[j][0] = s0; sacc[j][1] = s1; sacc[j][2] = s2; sacc[j][3] = s3;
            mx0 = fmaxf(mx0, fmaxf(s0, s1));
            mx1 = fmaxf(mx1, fmaxf(s2, s3));
        }
        mx0 = fmaxf(mx0, __shfl_xor_sync(0xFFFFFFFFu, mx0, 1));
        mx0 = fmaxf(mx0, __shfl_xor_sync(0xFFFFFFFFu, mx0, 2));
        mx1 = fmaxf(mx1, __shfl_xor_sync(0xFFFFFFFFu, mx1, 1));
        mx1 = fmaxf(mx1, __shfl_xor_sync(0xFFFFFFFFu, mx1, 2));
        float mn0 = fmaxf(m0r, mx0), mn1 = fmaxf(m1r, mx1);
        float cr0 = exp2f(m0r - mn0), cr1 = exp2f(m1r - mn1);
        m0r = mn0; m1r = mn1;
        l0 *= cr0; l1 *= cr1;
#pragma unroll
        for (int j = 0; j < 8; j++) {
            float p0 = exp2f(sacc[j][0] - mn0);
            float p1 = exp2f(sacc[j][1] - mn0);
            float p2 = exp2f(sacc[j][2] - mn1);
            float p3 = exp2f(sacc[j][3] - mn1);
            l0 += p0 + p1; l1 += p2 + p3;
            sacc[j][0] = p0; sacc[j][1] = p1; sacc[j][2] = p2; sacc[j][3] = p3;
        }
#pragma unroll
        for (int j = 0; j < 8; j++) {
            oacc[j][0] *= cr0; oacc[j][1] *= cr0;
            oacc[j][2] *= cr1; oacc[j][3] *= cr1;
        }

        uint32_t pa[4][4];
#pragma unroll
        for (int t = 0; t < 4; t++) {
            pa[t][0] = pack_h2(sacc[2 * t][0],     sacc[2 * t][1]);
            pa[t][1] = pack_h2(sacc[2 * t][2],     sacc[2 * t][3]);
            pa[t][2] = pack_h2(sacc[2 * t + 1][0], sacc[2 * t + 1][1]);
            pa[t][3] = pack_h2(sacc[2 * t + 1][2], sacc[2 * t + 1][3]);
        }

#pragma unroll
        for (int g = 0; g < 4; g++) {
            const int cv = 2 * g + vc8h;
#pragma unroll
            for (int ks = 0; ks < 4; ks++) {
                uint32_t vf[4];
                const int rowV = 16 * ks + rVl;
                const uint32_t voff = (uint32_t)(cv * 8 + (rowV >> 3)) * 128
                                    + (((rowV & 7) ^ cv) * 16);
                ldm4t(vf, Vs + voff);
                mma16816h(oacc[2 * g],     pa[ks], vf);
                mma16816h(oacc[2 * g + 1], pa[ks], vf + 2);
            }
        }
    }

    l0 += __shfl_xor_sync(0xFFFFFFFFu, l0, 1);
    l0 += __shfl_xor_sync(0xFFFFFFFFu, l0, 2);
    l1 += __shfl_xor_sync(0xFFFFFFFFu, l1, 1);
    l1 += __shfl_xor_sync(0xFFFFFFFFu, l1, 2);
    const float iv0 = 1.0f / l0, iv1 = 1.0f / l1;
    const size_t gr0 = (rbase + row0) * C_;
    const size_t gr1 = (rbase + row1) * C_;
#pragma unroll
    for (int j = 0; j < 8; j++) {
        int col = h * DH_ + j * 8 + (lane & 3) * 2;
        *(uint32_t*)(oh + gr0 + col) = pack_h2(oacc[j][0] * iv0, oacc[j][1] * iv0);
        *(uint32_t*)(oh + gr1 + col) = pack_h2(oacc[j][2] * iv1, oacc[j][3] * iv1);
    }
}

// ---------------------------------------------------------------------------
extern "C" void kernel_launch(void* const* d_in, const int* in_sizes, int n_in,
                              void* d_out, int out_size)
{
    const float* x     = (const float*)d_in[0];
    const float* w_qkv = (const float*)d_in[1];
    const float* w_o   = (const float*)d_in[2];
    float* out = (float*)d_out;

    __half *xh, *qkvh, *wqh, *woh;
    cudaGetSymbolAddress((void**)&xh,   g_xh);
    cudaGetSymbolAddress((void**)&qkvh, g_qkvh);
    cudaGetSymbolAddress((void**)&wqh,  g_wqh);
    cudaGetSymbolAddress((void**)&woh,  g_woh);

    cudaFuncSetAttribute(gemm_mma, cudaFuncAttributeMaxDynamicSharedMemorySize, GEMM_SMEM);
    cudaFuncSetAttribute(attn_mma, cudaFuncAttributeMaxDynamicSharedMemorySize, ATT_SMEM);

    // 0) fp16 conversions
    to_h16<<<(M_ * C_ + 255) / 256, 256>>>(x, xh, M_ * C_);
    transT_h16<<<dim3(C3_ / 32, C_ / 32), dim3(32, 8)>>>(w_qkv, wqh, C_, C3_);
    transT_h16<<<dim3(C_ / 32,  C_ / 32), dim3(32, 8)>>>(w_o,   woh, C_, C_);

    // 1) qkv = x @ w_qkv  (single product, fp16 out)
    gemm_mma<<<dim3(C3_ / 128, M_ / 256), 256, GEMM_SMEM>>>(
        xh, wqh, nullptr, qkvh, C3_);

    // 2) flash attention (all single product); O -> xh (fp16)
    attn_mma<<<dim3(T_ / AQT, H_, B_), 256, ATT_SMEM>>>(qkvh, xh);

    // 3) out = O @ w_o (single product, fp32 out)
    gemm_mma<<<dim3(C_ / 128, M_ / 256), 256, GEMM_SMEM>>>(
        xh, woh, out, nullptr, C_);
}

// round 16
// speedup vs baseline: 1.0496x; 1.0496x over previous
#include <cuda_runtime.h>
#include <cuda_fp16.h>
#include <cstdint>

#define B_   4
#define T_   2048
#define C_   1024
#define H_   16
#define DH_  64
#define C3_  3072
#define M_   (B_*T_)      // 8192 rows
#define K_   1024

// ---------------------------------------------------------------------------
// Scratch (no cudaMalloc). g_xh reused for attention fp16 output (x dead by then).
// ---------------------------------------------------------------------------
__device__ __half g_xh[(size_t)M_ * C_];
__device__ __half g_qkvh[(size_t)M_ * C3_];   // Q,K,V (fp16, single)
__device__ __half g_wqh[(size_t)C3_ * C_];    // W_qkv^T fp16
__device__ __half g_woh[(size_t)C_ * C_];     // W_o^T fp16

// ---------------------------------------------------------------------------
__device__ __forceinline__ uint32_t smem_u32(const void* p) {
    uint32_t a;
    asm("{ .reg .u64 t; cvta.to.shared.u64 t, %1; cvt.u32.u64 %0, t; }" : "=r"(a) : "l"(p));
    return a;
}
__device__ __forceinline__ void cpa16(uint32_t dst, const void* src) {
    asm volatile("cp.async.cg.shared.global [%0], [%1], 16;" :: "r"(dst), "l"(src));
}
__device__ __forceinline__ void ldm4(uint32_t* r, uint32_t addr) {
    asm volatile("ldmatrix.sync.aligned.m8n8.x4.shared.b16 {%0,%1,%2,%3}, [%4];"
                 : "=r"(r[0]), "=r"(r[1]), "=r"(r[2]), "=r"(r[3]) : "r"(addr));
}
__device__ __forceinline__ void ldm4t(uint32_t* r, uint32_t addr) {
    asm volatile("ldmatrix.sync.aligned.m8n8.x4.trans.shared.b16 {%0,%1,%2,%3}, [%4];"
                 : "=r"(r[0]), "=r"(r[1]), "=r"(r[2]), "=r"(r[3]) : "r"(addr));
}
__device__ __forceinline__ void mma16816h(float* d, const uint32_t* a, const uint32_t* b) {
    asm volatile("mma.sync.aligned.m16n8k16.row.col.f32.f16.f16.f32 "
                 "{%0,%1,%2,%3}, {%4,%5,%6,%7}, {%8,%9}, {%0,%1,%2,%3};"
                 : "+f"(d[0]), "+f"(d[1]), "+f"(d[2]), "+f"(d[3])
                 : "r"(a[0]), "r"(a[1]), "r"(a[2]), "r"(a[3]), "r"(b[0]), "r"(b[1]));
}
__device__ __forceinline__ uint32_t pack_h2(float a, float b) {
    uint32_t r;
    asm("cvt.rn.f16x2.f32 %0, %1, %2;" : "=r"(r) : "f"(b), "f"(a));
    return r;
}

// ---------------------------------------------------------------------------
__global__ void to_h16(const float* __restrict__ x, __half* __restrict__ o, int n)
{
    int i = blockIdx.x * blockDim.x + threadIdx.x;
    if (i < n) o[i] = __float2half_rn(x[i]);
}

// Transpose: W[K][N] fp32 -> T[N][K] fp16
__global__ void transT_h16(const float* __restrict__ W,
                           __half* __restrict__ Th, int K, int N)
{
    __shared__ float t[32][33];
    int n0 = blockIdx.x * 32, k0 = blockIdx.y * 32;
    int tx = threadIdx.x, ty = threadIdx.y;
    for (int r = ty; r < 32; r += 8)
        t[r][tx] = W[(size_t)(k0 + r) * N + n0 + tx];
    __syncthreads();
    for (int r = ty; r < 32; r += 8)
        Th[(size_t)(n0 + r) * K + k0 + tx] = __float2half_rn(t[tx][r]);
}

// ---------------------------------------------------------------------------
// mma.sync fp16 GEMM (R14 best-measured config, unchanged):
// CTA 128x128, BK=32, 3-stage cp.async, XOR swizzle, fragment double-buffer.
// ---------------------------------------------------------------------------
#define BKSLAB     32
#define OPB        8192
#define STAGEB     (2 * OPB)            // A, B
#define GSTAGES    3
#define GEMM_SMEM  (GSTAGES * STAGEB)   // 49152 B

__global__ void __launch_bounds__(256, 2) gemm_mma(
    const __half* __restrict__ Ah_, const __half* __restrict__ Bh_,
    float* __restrict__ Cf, __half* __restrict__ Chi, int N)
{
    extern __shared__ char smem[];
    const uint32_t sb = smem_u32(smem);
    const int tid  = threadIdx.x;
    const int m0   = blockIdx.y * 128;
    const int n0   = blockIdx.x * 128;
    const int wid  = tid >> 5, lane = tid & 31;
    const int warp_m = (wid & 1) * 64;
    const int warp_n = (wid >> 1) * 32;

    const __half* pA  = Ah_ + (size_t)m0 * K_;
    const __half* pBh = Bh_ + (size_t)n0 * K_;

    auto load_stage = [&](int it, int slot) {
        const uint32_t st = sb + slot * STAGEB;
        const int kb = it * BKSLAB;
#pragma unroll
        for (int i = 0; i < 4; i++) {
            const __half* base = (i < 2) ? pA : pBh;
            int w   = ((i & 1) << 8) + tid;
            int row = w >> 2;
            int c   = w & 3;
            const void* src = base + (size_t)row * K_ + kb + c * 8;
            uint32_t dst = st + (i >> 1) * OPB + (c * 16 + (row >> 3)) * 128
                         + (((row & 7) ^ (c << 1)) * 16);
            cpa16(dst, src);
        }
        asm volatile("cp.async.commit_group;" ::: "memory");
    };

    float acc[4][4][4];
#pragma unroll
    for (int a = 0; a < 4; a++)
#pragma unroll
        for (int b = 0; b < 4; b++)
#pragma unroll
            for (int c = 0; c < 4; c++) acc[a][b][c] = 0.f;

    const int mA  = warp_m + (lane & 15);
    const int mA8 = mA >> 3, mA7 = mA & 7;
    const int k8A = lane >> 4;
    const int nB  = warp_n + ((lane >> 4) << 3) + (lane & 7);
    const int nB8 = nB >> 3, nB7 = nB & 7;
    const int k8B = (lane >> 3) & 1;

    auto offA = [&](int ks) {
        const int cA = ks * 2 + k8A;
        return (uint32_t)(cA * 16 + mA8) * 128 + ((mA7 ^ (cA << 1)) * 16);
    };
    auto offB = [&](int ks) {
        const int cB = ks * 2 + k8B;
        return (uint32_t)(cB * 16 + nB8) * 128 + ((nB7 ^ (cB << 1)) * 16);
    };

    load_stage(0, 0);
    load_stage(1, 1);

    uint32_t ah[2][4][4], bb[2][4][2];

    const int NIT = K_ / BKSLAB;
    for (int it = 0; it < NIT; it++) {
        if (it + 1 < NIT) asm volatile("cp.async.wait_group 1;" ::: "memory");
        else              asm volatile("cp.async.wait_group 0;" ::: "memory");
        __syncthreads();

        const uint32_t st = sb + (it % GSTAGES) * STAGEB;
        const uint32_t AH = st, BH = st + OPB;

#pragma unroll
        for (int mt = 0; mt < 4; mt++)
            ldm4(ah[0][mt], AH + offA(0) + mt * 256);
#pragma unroll
        for (int j = 0; j < 2; j++)
            ldm4(&bb[0][j * 2][0], BH + offB(0) + j * 256);

        if (it + 2 < NIT) load_stage(it + 2, (it + 2) % GSTAGES);

#pragma unroll
        for (int ks = 0; ks < 2; ks++) {
            if (ks == 0) {
#pragma unroll
                for (int mt = 0; mt < 4; mt++)
                    ldm4(ah[1][mt], AH + offA(1) + mt * 256);
#pragma unroll
                for (int j = 0; j < 2; j++)
                    ldm4(&bb[1][j * 2][0], BH + offB(1) + j * 256);
            }
#pragma unroll
            for (int mt = 0; mt < 4; mt++)
#pragma unroll
                for (int nt = 0; nt < 4; nt++)
                    mma16816h(acc[mt][nt], ah[ks][mt], bb[ks][nt]);
        }
    }

    const int r0 = m0 + warp_m + (lane >> 2);
    const int c0 = n0 + warp_n + (lane & 3) * 2;
    if (Chi) {
#pragma unroll
        for (int mt = 0; mt < 4; mt++) {
#pragma unroll
            for (int nt = 0; nt < 4; nt++) {
                size_t o0 = (size_t)(r0 + mt * 16) * N + c0 + nt * 8;
                size_t o1 = o0 + (size_t)8 * N;
                *(uint32_t*)(Chi + o0) = pack_h2(acc[mt][nt][0], acc[mt][nt][1]);
                *(uint32_t*)(Chi + o1) = pack_h2(acc[mt][nt][2], acc[mt][nt][3]);
            }
        }
    } else {
#pragma unroll
        for (int mt = 0; mt < 4; mt++) {
#pragma unroll
            for (int nt = 0; nt < 4; nt++) {
                float* p = Cf + (size_t)(r0 + mt * 16) * N + c0 + nt * 8;
                *(float2*)p                   = make_float2(acc[mt][nt][0], acc[mt][nt][1]);
                *(float2*)(p + (size_t)8 * N) = make_float2(acc[mt][nt][2], acc[mt][nt][3]);
            }
        }
    }
}

// ---------------------------------------------------------------------------
// fp16 flash attention, causal + ALiBi, single product.
// Changes vs R12: Q fragments hoisted into registers (own cp.async group,
// loaded once before mainloop); big-first qt ordering for tail packing.
// ---------------------------------------------------------------------------
#define AQT       128
#define AKT       64
#define AOPB      8192
#define ASTAGEB   (2 * AOPB)             // K, V
#define ATT_SMEM  (16384 + 2 * ASTAGEB)  // 49152 B

__global__ void __launch_bounds__(256, 2) attn_mma(
    const __half* __restrict__ qkv, __half* __restrict__ oh)
{
    extern __shared__ char smem[];
    const uint32_t sb = smem_u32(smem);
    const uint32_t Qs = sb;
    const uint32_t ST0 = sb + 16384;

    const int tid  = threadIdx.x;
    const int wid  = tid >> 5, lane = tid & 31;
    const int b    = blockIdx.z;
    const int h    = blockIdx.y;
    const int qt   = (int)gridDim.x - 1 - (int)blockIdx.x;   // big-first
    const int q0   = qt * AQT;
    const int nkt  = 2 * qt + 2;
    const size_t rbase = (size_t)b * T_;

    const float LOG2E = 1.4426950408889634f;
    const float sc2 = LOG2E / 32.0f;
    const float sl2 = exp2f(-0.5f * (float)(h + 1)) * LOG2E;

    // Q tile in its own cp.async group (group committed first)
    for (int i = tid; i < 1024; i += 256) {
        int r = (i >> 3) & 127, c8 = i & 7;
        const void* src = qkv + (rbase + q0 + r) * C3_ + h * DH_ + c8 * 8;
        uint32_t dst = Qs + (c8 * 16 + (r >> 3)) * 128 + (((r & 7) ^ c8) * 16);
        cpa16(dst, src);
    }
    asm volatile("cp.async.commit_group;" ::: "memory");

    auto load_stage = [&](int kt, int slot) {
        const int k0 = kt * AKT;
        const uint32_t st = ST0 + slot * ASTAGEB;
        for (int i = tid; i < 1024; i += 256) {
            int op = i >> 9, r = (i >> 3) & 63, c8 = i & 7;
            int coloff = ((op == 0) ? C_ : 2 * C_) + h * DH_;
            const void* src = qkv + (rbase + k0 + r) * C3_ + coloff + c8 * 8;
            uint32_t dst = st + op * AOPB + (c8 * 8 + (r >> 3)) * 128 + (((r & 7) ^ c8) * 16);
            cpa16(dst, src);
        }
        asm volatile("cp.async.commit_group;" ::: "memory");
    };
    load_stage(0, 0);

    const int rA   = wid * 16 + (lane & 15);
    const int rA8  = rA >> 3, rA7 = rA & 7;
    const int qc8h = lane >> 4;
    const int nKl  = (lane & 7) + ((lane >> 4) << 3);
    const int kc8h = (lane >> 3) & 1;
    const int rVl  = (lane & 7) + (((lane >> 3) & 1) << 3);
    const int vc8h = lane >> 4;
    const int row0 = q0 + wid * 16 + (lane >> 2);
    const int row1 = row0 + 8;

    // Hoist Q fragments (invariant across kt): wait for Q group only
    asm volatile("cp.async.wait_group 1;" ::: "memory");
    __syncthreads();
    uint32_t qfr[4][4];
#pragma unroll
    for (int ks = 0; ks < 4; ks++) {
        const int cq = 2 * ks + qc8h;
        ldm4(qfr[ks], Qs + (uint32_t)(cq * 16 + rA8) * 128 + ((rA7 ^ cq) * 16));
    }

    float oacc[8][4];
#pragma unroll
    for (int j = 0; j < 8; j++)
#pragma unroll
        for (int c = 0; c < 4; c++) oacc[j][c] = 0.f;
    float m0r = -1e30f, m1r = -1e30f, l0 = 0.f, l1 = 0.f;

    for (int kt = 0; kt < nkt; kt++) {
        asm volatile("cp.async.wait_group 0;" ::: "memory");
        __syncthreads();
        if (kt + 1 < nkt) load_stage(kt + 1, (kt + 1) & 1);

        const int k0 = kt * AKT;
        const uint32_t st = ST0 + (kt & 1) * ASTAGEB;
        const uint32_t Ks = st, Vs = st + AOPB;

        float sacc[8][4];
#pragma unroll
        for (int j = 0; j < 8; j++)
#pragma unroll
            for (int c = 0; c < 4; c++) sacc[j][c] = 0.f;

#pragma unroll
        for (int ks = 0; ks < 4; ks++) {
            const int ck = 2 * ks + kc8h;
#pragma unroll
            for (int j = 0; j < 4; j++) {
                uint32_t kf[4];
                const int rowK = 16 * j + nKl;
                const uint32_t koff = (uint32_t)(ck * 8 + (rowK >> 3)) * 128
                                    + (((rowK & 7) ^ ck) * 16);
                ldm4(kf, Ks + koff);
                mma16816h(sacc[2 * j],     qfr[ks], kf);
                mma16816h(sacc[2 * j + 1], qfr[ks], kf + 2);
            }
        }

        float mx0 = -1e30f, mx1 = -1e30f;
#pragma unroll
        for (int j = 0; j < 8; j++) {
            int col = k0 + j * 8 + (lane & 3) * 2;
            float s0 = (col     <= row0) ? sacc[j][0] * sc2 + sl2 * (float)(col     - row0) : -1e30f;
            float s1 = (col + 1 <= row0) ? sacc[j][1] * sc2 + sl2 * (float)(col + 1 - row0) : -1e30f;
            float s2 = (col     <= row1) ? sacc[j][2] * sc2 + sl2 * (float)(col     - row1) : -1e30f;
            float s3 = (col + 1 <= row1) ? sacc[j][3] * sc2 + sl2 * (float)(col + 1 - row1) : -1e30f;
            sacc[j][0] = s0; sacc[j][1] = s1; sacc[j][2] = s2; sacc[j][3] = s3;
            mx0 = fmaxf(mx0, fmaxf(s0, s1));
            mx1 = fmaxf(mx1, fmaxf(s2, s3));
        }
        mx0 = fmaxf(mx0, __shfl_xor_sync(0xFFFFFFFFu, mx0, 1));
        mx0 = fmaxf(mx0, __shfl_xor_sync(0xFFFFFFFFu, mx0, 2));
        mx1 = fmaxf(mx1, __shfl_xor_sync(0xFFFFFFFFu, mx1, 1));
        mx1 = fmaxf(mx1, __shfl_xor_sync(0xFFFFFFFFu, mx1, 2));
        float mn0 = fmaxf(m0r, mx0), mn1 = fmaxf(m1r, mx1);
        float cr0 = exp2f(m0r - mn0), cr1 = exp2f(m1r - mn1);
        m0r = mn0; m1r = mn1;
        l0 *= cr0; l1 *= cr1;
#pragma unroll
        for (int j = 0; j < 8; j++) {
            float p0 = exp2f(sacc[j][0] - mn0);
            float p1 = exp2f(sacc[j][1] - mn0);
            float p2 = exp2f(sacc[j][2] - mn1);
            float p3 = exp2f(sacc[j][3] - mn1);
            l0 += p0 + p1; l1 += p2 + p3;
            sacc[j][0] = p0; sacc[j][1] = p1; sacc[j][2] = p2; sacc[j][3] = p3;
        }
#pragma unroll
        for (int j = 0; j < 8; j++) {
            oacc[j][0] *= cr0; oacc[j][1] *= cr0;
            oacc[j][2] *= cr1; oacc[j][3] *= cr1;
        }

        uint32_t pa[4][4];
#pragma unroll
        for (int t = 0; t < 4; t++) {
            pa[t][0] = pack_h2(sacc[2 * t][0],     sacc[2 * t][1]);
            pa[t][1] = pack_h2(sacc[2 * t][2],     sacc[2 * t][3]);
            pa[t][2] = pack_h2(sacc[2 * t + 1][0], sacc[2 * t + 1][1]);
            pa[t][3] = pack_h2(sacc[2 * t + 1][2], sacc[2 * t + 1][3]);
        }

#pragma unroll
        for (int g = 0; g < 4; g++) {
            const int cv = 2 * g + vc8h;
#pragma unroll
            for (int ks = 0; ks < 4; ks++) {
                uint32_t vf[4];
                const int rowV = 16 * ks + rVl;
                const uint32_t voff = (uint32_t)(cv * 8 + (rowV >> 3)) * 128
                                    + (((rowV & 7) ^ cv) * 16);
                ldm4t(vf, Vs + voff);
                mma16816h(oacc[2 * g],     pa[ks], vf);
                mma16816h(oacc[2 * g + 1], pa[ks], vf + 2);
            }
        }
    }

    l0 += __shfl_xor_sync(0xFFFFFFFFu, l0, 1);
    l0 += __shfl_xor_sync(0xFFFFFFFFu, l0, 2);
    l1 += __shfl_xor_sync(0xFFFFFFFFu, l1, 1);
    l1 += __shfl_xor_sync(0xFFFFFFFFu, l1, 2);
    const float iv0 = 1.0f / l0, iv1 = 1.0f / l1;
    const size_t gr0 = (rbase + row0) * C_;
    const size_t gr1 = (rbase + row1) * C_;
#pragma unroll
    for (int j = 0; j < 8; j++) {
        int col = h * DH_ + j * 8 + (lane & 3) * 2;
        *(uint32_t*)(oh + gr0 + col) = pack_h2(oacc[j][0] * iv0, oacc[j][1] * iv0);
        *(uint32_t*)(oh + gr1 + col) = pack_h2(oacc[j][2] * iv1, oacc[j][3] * iv1);
    }
}

// ---------------------------------------------------------------------------
extern "C" void kernel_launch(void* const* d_in, const int* in_sizes, int n_in,
                              void* d_out, int out_size)
{
    const float* x     = (const float*)d_in[0];
    const float* w_qkv = (const float*)d_in[1];
    const float* w_o   = (const float*)d_in[2];
    float* out = (float*)d_out;

    __half *xh, *qkvh, *wqh, *woh;
    cudaGetSymbolAddress((void**)&xh,   g_xh);
    cudaGetSymbolAddress((void**)&qkvh, g_qkvh);
    cudaGetSymbolAddress((void**)&wqh,  g_wqh);
    cudaGetSymbolAddress((void**)&woh,  g_woh);

    cudaFuncSetAttribute(gemm_mma, cudaFuncAttributeMaxDynamicSharedMemorySize, GEMM_SMEM);
    cudaFuncSetAttribute(attn_mma, cudaFuncAttributeMaxDynamicSharedMemorySize, ATT_SMEM);

    // 0) fp16 conversions
    to_h16<<<(M_ * C_ + 255) / 256, 256>>>(x, xh, M_ * C_);
    transT_h16<<<dim3(C3_ / 32, C_ / 32), dim3(32, 8)>>>(w_qkv, wqh, C_, C3_);
    transT_h16<<<dim3(C_ / 32,  C_ / 32), dim3(32, 8)>>>(w_o,   woh, C_, C_);

    // 1) qkv = x @ w_qkv  (single product, fp16 out)
    gemm_mma<<<dim3(C3_ / 128, M_ / 128), 256, GEMM_SMEM>>>(
        xh, wqh, nullptr, qkvh, C3_);

    // 2) flash attention (single product); O -> xh (fp16)
    attn_mma<<<dim3(T_ / AQT, H_, B_), 256, ATT_SMEM>>>(qkvh, xh);

    // 3) out = O @ w_o (single product, fp32 out)
    gemm_mma<<<dim3(C_ / 128, M_ / 128), 256, GEMM_SMEM>>>(
        xh, woh, out, nullptr, C_);
}

// round 17
// speedup vs baseline: 1.0812x; 1.0302x over previous
#include <cuda_runtime.h>
#include <cuda_fp16.h>
#include <cstdint>

#define B_   4
#define T_   2048
#define C_   1024
#define H_   16
#define DH_  64
#define C3_  3072
#define M_   (B_*T_)      // 8192 rows
#define K_   1024

// ---------------------------------------------------------------------------
// Scratch (no cudaMalloc). g_xh reused for attention fp16 output (x dead by then).
// ---------------------------------------------------------------------------
__device__ __half g_xh[(size_t)M_ * C_];
__device__ __half g_qkvh[(size_t)M_ * C3_];   // Q,K,V (fp16, single)
__device__ __half g_wqh[(size_t)C3_ * C_];    // W_qkv^T fp16
__device__ __half g_woh[(size_t)C_ * C_];     // W_o^T fp16

// ---------------------------------------------------------------------------
__device__ __forceinline__ uint32_t smem_u32(const void* p) {
    uint32_t a;
    asm("{ .reg .u64 t; cvta.to.shared.u64 t, %1; cvt.u32.u64 %0, t; }" : "=r"(a) : "l"(p));
    return a;
}
__device__ __forceinline__ void cpa16(uint32_t dst, const void* src) {
    asm volatile("cp.async.cg.shared.global [%0], [%1], 16;" :: "r"(dst), "l"(src));
}
__device__ __forceinline__ void ldm4(uint32_t* r, uint32_t addr) {
    asm volatile("ldmatrix.sync.aligned.m8n8.x4.shared.b16 {%0,%1,%2,%3}, [%4];"
                 : "=r"(r[0]), "=r"(r[1]), "=r"(r[2]), "=r"(r[3]) : "r"(addr));
}
__device__ __forceinline__ void ldm4t(uint32_t* r, uint32_t addr) {
    asm volatile("ldmatrix.sync.aligned.m8n8.x4.trans.shared.b16 {%0,%1,%2,%3}, [%4];"
                 : "=r"(r[0]), "=r"(r[1]), "=r"(r[2]), "=r"(r[3]) : "r"(addr));
}
__device__ __forceinline__ void mma16816h(float* d, const uint32_t* a, const uint32_t* b) {
    asm volatile("mma.sync.aligned.m16n8k16.row.col.f32.f16.f16.f32 "
                 "{%0,%1,%2,%3}, {%4,%5,%6,%7}, {%8,%9}, {%0,%1,%2,%3};"
                 : "+f"(d[0]), "+f"(d[1]), "+f"(d[2]), "+f"(d[3])
                 : "r"(a[0]), "r"(a[1]), "r"(a[2]), "r"(a[3]), "r"(b[0]), "r"(b[1]));
}
__device__ __forceinline__ uint32_t pack_h2(float a, float b) {
    uint32_t r;
    asm("cvt.rn.f16x2.f32 %0, %1, %2;" : "=r"(r) : "f"(b), "f"(a));
    return r;
}
// exp2 of a packed fp16x2 (one MUFU op for two values)
__device__ __forceinline__ uint32_t h2exp2u(uint32_t x) {
    uint32_t r;
    asm("ex2.approx.f16x2 %0, %1;" : "=r"(r) : "r"(x));
    return r;
}

// ---------------------------------------------------------------------------
__global__ void to_h16(const float* __restrict__ x, __half* __restrict__ o, int n)
{
    int i = blockIdx.x * blockDim.x + threadIdx.x;
    if (i < n) o[i] = __float2half_rn(x[i]);
}

// Transpose: W[K][N] fp32 -> T[N][K] fp16
__global__ void transT_h16(const float* __restrict__ W,
                           __half* __restrict__ Th, int K, int N)
{
    __shared__ float t[32][33];
    int n0 = blockIdx.x * 32, k0 = blockIdx.y * 32;
    int tx = threadIdx.x, ty = threadIdx.y;
    for (int r = ty; r < 32; r += 8)
        t[r][tx] = W[(size_t)(k0 + r) * N + n0 + tx];
    __syncthreads();
    for (int r = ty; r < 32; r += 8)
        Th[(size_t)(n0 + r) * K + k0 + tx] = __float2half_rn(t[tx][r]);
}

// ---------------------------------------------------------------------------
// mma.sync fp16 GEMM (R14 best-measured config, unchanged):
// CTA 128x128, BK=32, 3-stage cp.async, XOR swizzle, fragment double-buffer.
// ---------------------------------------------------------------------------
#define BKSLAB     32
#define OPB        8192
#define STAGEB     (2 * OPB)            // A, B
#define GSTAGES    3
#define GEMM_SMEM  (GSTAGES * STAGEB)   // 49152 B

__global__ void __launch_bounds__(256, 2) gemm_mma(
    const __half* __restrict__ Ah_, const __half* __restrict__ Bh_,
    float* __restrict__ Cf, __half* __restrict__ Chi, int N)
{
    extern __shared__ char smem[];
    const uint32_t sb = smem_u32(smem);
    const int tid  = threadIdx.x;
    const int m0   = blockIdx.y * 128;
    const int n0   = blockIdx.x * 128;
    const int wid  = tid >> 5, lane = tid & 31;
    const int warp_m = (wid & 1) * 64;
    const int warp_n = (wid >> 1) * 32;

    const __half* pA  = Ah_ + (size_t)m0 * K_;
    const __half* pBh = Bh_ + (size_t)n0 * K_;

    auto load_stage = [&](int it, int slot) {
        const uint32_t st = sb + slot * STAGEB;
        const int kb = it * BKSLAB;
#pragma unroll
        for (int i = 0; i < 4; i++) {
            const __half* base = (i < 2) ? pA : pBh;
            int w   = ((i & 1) << 8) + tid;
            int row = w >> 2;
            int c   = w & 3;
            const void* src = base + (size_t)row * K_ + kb + c * 8;
            uint32_t dst = st + (i >> 1) * OPB + (c * 16 + (row >> 3)) * 128
                         + (((row & 7) ^ (c << 1)) * 16);
            cpa16(dst, src);
        }
        asm volatile("cp.async.commit_group;" ::: "memory");
    };

    float acc[4][4][4];
#pragma unroll
    for (int a = 0; a < 4; a++)
#pragma unroll
        for (int b = 0; b < 4; b++)
#pragma unroll
            for (int c = 0; c < 4; c++) acc[a][b][c] = 0.f;

    const int mA  = warp_m + (lane & 15);
    const int mA8 = mA >> 3, mA7 = mA & 7;
    const int k8A = lane >> 4;
    const int nB  = warp_n + ((lane >> 4) << 3) + (lane & 7);
    const int nB8 = nB >> 3, nB7 = nB & 7;
    const int k8B = (lane >> 3) & 1;

    auto offA = [&](int ks) {
        const int cA = ks * 2 + k8A;
        return (uint32_t)(cA * 16 + mA8) * 128 + ((mA7 ^ (cA << 1)) * 16);
    };
    auto offB = [&](int ks) {
        const int cB = ks * 2 + k8B;
        return (uint32_t)(cB * 16 + nB8) * 128 + ((nB7 ^ (cB << 1)) * 16);
    };

    load_stage(0, 0);
    load_stage(1, 1);

    uint32_t ah[2][4][4], bb[2][4][2];

    const int NIT = K_ / BKSLAB;
    for (int it = 0; it < NIT; it++) {
        if (it + 1 < NIT) asm volatile("cp.async.wait_group 1;" ::: "memory");
        else              asm volatile("cp.async.wait_group 0;" ::: "memory");
        __syncthreads();

        const uint32_t st = sb + (it % GSTAGES) * STAGEB;
        const uint32_t AH = st, BH = st + OPB;

#pragma unroll
        for (int mt = 0; mt < 4; mt++)
            ldm4(ah[0][mt], AH + offA(0) + mt * 256);
#pragma unroll
        for (int j = 0; j < 2; j++)
            ldm4(&bb[0][j * 2][0], BH + offB(0) + j * 256);

        if (it + 2 < NIT) load_stage(it + 2, (it + 2) % GSTAGES);

#pragma unroll
        for (int ks = 0; ks < 2; ks++) {
            if (ks == 0) {
#pragma unroll
                for (int mt = 0; mt < 4; mt++)
                    ldm4(ah[1][mt], AH + offA(1) + mt * 256);
#pragma unroll
                for (int j = 0; j < 2; j++)
                    ldm4(&bb[1][j * 2][0], BH + offB(1) + j * 256);
            }
#pragma unroll
            for (int mt = 0; mt < 4; mt++)
#pragma unroll
                for (int nt = 0; nt < 4; nt++)
                    mma16816h(acc[mt][nt], ah[ks][mt], bb[ks][nt]);
        }
    }

    const int r0 = m0 + warp_m + (lane >> 2);
    const int c0 = n0 + warp_n + (lane & 3) * 2;
    if (Chi) {
#pragma unroll
        for (int mt = 0; mt < 4; mt++) {
#pragma unroll
            for (int nt = 0; nt < 4; nt++) {
                size_t o0 = (size_t)(r0 + mt * 16) * N + c0 + nt * 8;
                size_t o1 = o0 + (size_t)8 * N;
                *(uint32_t*)(Chi + o0) = pack_h2(acc[mt][nt][0], acc[mt][nt][1]);
                *(uint32_t*)(Chi + o1) = pack_h2(acc[mt][nt][2], acc[mt][nt][3]);
            }
        }
    } else {
#pragma unroll
        for (int mt = 0; mt < 4; mt++) {
#pragma unroll
            for (int nt = 0; nt < 4; nt++) {
                float* p = Cf + (size_t)(r0 + mt * 16) * N + c0 + nt * 8;
                *(float2*)p                   = make_float2(acc[mt][nt][0], acc[mt][nt][1]);
                *(float2*)(p + (size_t)8 * N) = make_float2(acc[mt][nt][2], acc[mt][nt][3]);
            }
        }
    }
}

// ---------------------------------------------------------------------------
// fp16 flash attention, causal + ALiBi, single product.
// Softmax exps in fp16x2 (ex2.approx.f16x2): half the MUFU ops; the exp
// output IS the P fragment. Row-sums accumulated in half2, folded to fp32.
// ---------------------------------------------------------------------------
#define AQT       128
#define AKT       64
#define AOPB      8192
#define ASTAGEB   (2 * AOPB)             // K, V
#define ATT_SMEM  (16384 + 2 * ASTAGEB)  // 49152 B

__global__ void __launch_bounds__(256, 2) attn_mma(
    const __half* __restrict__ qkv, __half* __restrict__ oh)
{
    extern __shared__ char smem[];
    const uint32_t sb = smem_u32(smem);
    const uint32_t Qs = sb;
    const uint32_t ST0 = sb + 16384;

    const int tid  = threadIdx.x;
    const int wid  = tid >> 5, lane = tid & 31;
    const int b    = blockIdx.z;
    const int h    = blockIdx.y;
    const int qt   = (int)gridDim.x - 1 - (int)blockIdx.x;   // big-first
    const int q0   = qt * AQT;
    const int nkt  = 2 * qt + 2;
    const size_t rbase = (size_t)b * T_;

    const float LOG2E = 1.4426950408889634f;
    const float sc2 = LOG2E / 32.0f;
    const float sl2 = exp2f(-0.5f * (float)(h + 1)) * LOG2E;

    // Q tile in its own cp.async group
    for (int i = tid; i < 1024; i += 256) {
        int r = (i >> 3) & 127, c8 = i & 7;
        const void* src = qkv + (rbase + q0 + r) * C3_ + h * DH_ + c8 * 8;
        uint32_t dst = Qs + (c8 * 16 + (r >> 3)) * 128 + (((r & 7) ^ c8) * 16);
        cpa16(dst, src);
    }
    asm volatile("cp.async.commit_group;" ::: "memory");

    auto load_stage = [&](int kt, int slot) {
        const int k0 = kt * AKT;
        const uint32_t st = ST0 + slot * ASTAGEB;
        for (int i = tid; i < 1024; i += 256) {
            int op = i >> 9, r = (i >> 3) & 63, c8 = i & 7;
            int coloff = ((op == 0) ? C_ : 2 * C_) + h * DH_;
            const void* src = qkv + (rbase + k0 + r) * C3_ + coloff + c8 * 8;
            uint32_t dst = st + op * AOPB + (c8 * 8 + (r >> 3)) * 128 + (((r & 7) ^ c8) * 16);
            cpa16(dst, src);
        }
        asm volatile("cp.async.commit_group;" ::: "memory");
    };
    load_stage(0, 0);

    const int rA   = wid * 16 + (lane & 15);
    const int rA8  = rA >> 3, rA7 = rA & 7;
    const int qc8h = lane >> 4;
    const int nKl  = (lane & 7) + ((lane >> 4) << 3);
    const int kc8h = (lane >> 3) & 1;
    const int rVl  = (lane & 7) + (((lane >> 3) & 1) << 3);
    const int vc8h = lane >> 4;
    const int row0 = q0 + wid * 16 + (lane >> 2);
    const int row1 = row0 + 8;

    // Hoist Q fragments (invariant across kt)
    asm volatile("cp.async.wait_group 1;" ::: "memory");
    __syncthreads();
    uint32_t qfr[4][4];
#pragma unroll
    for (int ks = 0; ks < 4; ks++) {
        const int cq = 2 * ks + qc8h;
        ldm4(qfr[ks], Qs + (uint32_t)(cq * 16 + rA8) * 128 + ((rA7 ^ cq) * 16));
    }

    float oacc[8][4];
#pragma unroll
    for (int j = 0; j < 8; j++)
#pragma unroll
        for (int c = 0; c < 4; c++) oacc[j][c] = 0.f;
    float m0r = -1e30f, m1r = -1e30f, l0 = 0.f, l1 = 0.f;

    for (int kt = 0; kt < nkt; kt++) {
        asm volatile("cp.async.wait_group 0;" ::: "memory");
        __syncthreads();
        if (kt + 1 < nkt) load_stage(kt + 1, (kt + 1) & 1);

        const int k0 = kt * AKT;
        const uint32_t st = ST0 + (kt & 1) * ASTAGEB;
        const uint32_t Ks = st, Vs = st + AOPB;

        float sacc[8][4];
#pragma unroll
        for (int j = 0; j < 8; j++)
#pragma unroll
            for (int c = 0; c < 4; c++) sacc[j][c] = 0.f;

#pragma unroll
        for (int ks = 0; ks < 4; ks++) {
            const int ck = 2 * ks + kc8h;
#pragma unroll
            for (int j = 0; j < 4; j++) {
                uint32_t kf[4];
                const int rowK = 16 * j + nKl;
                const uint32_t koff = (uint32_t)(ck * 8 + (rowK >> 3)) * 128
                                    + (((rowK & 7) ^ ck) * 16);
                ldm4(kf, Ks + koff);
                mma16816h(sacc[2 * j],     qfr[ks], kf);
                mma16816h(sacc[2 * j + 1], qfr[ks], kf + 2);
            }
        }

        // scale + ALiBi + causal mask (log2 domain), running max
        float mx0 = -1e30f, mx1 = -1e30f;
#pragma unroll
        for (int j = 0; j < 8; j++) {
            int col = k0 + j * 8 + (lane & 3) * 2;
            float s0 = (col     <= row0) ? sacc[j][0] * sc2 + sl2 * (float)(col     - row0) : -1e30f;
            float s1 = (col + 1 <= row0) ? sacc[j][1] * sc2 + sl2 * (float)(col + 1 - row0) : -1e30f;
            float s2 = (col     <= row1) ? sacc[j][2] * sc2 + sl2 * (float)(col     - row1) : -1e30f;
            float s3 = (col + 1 <= row1) ? sacc[j][3] * sc2 + sl2 * (float)(col + 1 - row1) : -1e30f;
            sacc[j][0] = s0; sacc[j][1] = s1; sacc[j][2] = s2; sacc[j][3] = s3;
            mx0 = fmaxf(mx0, fmaxf(s0, s1));
            mx1 = fmaxf(mx1, fmaxf(s2, s3));
        }
        mx0 = fmaxf(mx0, __shfl_xor_sync(0xFFFFFFFFu, mx0, 1));
        mx0 = fmaxf(mx0, __shfl_xor_sync(0xFFFFFFFFu, mx0, 2));
        mx1 = fmaxf(mx1, __shfl_xor_sync(0xFFFFFFFFu, mx1, 1));
        mx1 = fmaxf(mx1, __shfl_xor_sync(0xFFFFFFFFu, mx1, 2));
        float mn0 = fmaxf(m0r, mx0), mn1 = fmaxf(m1r, mx1);
        float cr0 = exp2f(m0r - mn0), cr1 = exp2f(m1r - mn1);
        m0r = mn0; m1r = mn1;
        l0 *= cr0; l1 *= cr1;
#pragma unroll
        for (int j = 0; j < 8; j++) {
            oacc[j][0] *= cr0; oacc[j][1] *= cr0;
            oacc[j][2] *= cr1; oacc[j][3] *= cr1;
        }

        // P fragments via fp16x2 exp; half2 row-sums (masked -> -inf -> 0)
        uint32_t pa[4][4];
        __half2 lh0 = __float2half2_rn(0.f), lh1 = __float2half2_rn(0.f);
#pragma unroll
        for (int t = 0; t < 4; t++) {
            pa[t][0] = h2exp2u(pack_h2(sacc[2 * t][0] - mn0,     sacc[2 * t][1] - mn0));
            pa[t][1] = h2exp2u(pack_h2(sacc[2 * t][2] - mn1,     sacc[2 * t][3] - mn1));
            pa[t][2] = h2exp2u(pack_h2(sacc[2 * t + 1][0] - mn0, sacc[2 * t + 1][1] - mn0));
            pa[t][3] = h2exp2u(pack_h2(sacc[2 * t + 1][2] - mn1, sacc[2 * t + 1][3] - mn1));
            lh0 = __hadd2(lh0, __hadd2(*(__half2*)&pa[t][0], *(__half2*)&pa[t][2]));
            lh1 = __hadd2(lh1, __hadd2(*(__half2*)&pa[t][1], *(__half2*)&pa[t][3]));
        }
        l0 += __low2float(lh0) + __high2float(lh0);
        l1 += __low2float(lh1) + __high2float(lh1);

#pragma unroll
        for (int g = 0; g < 4; g++) {
            const int cv = 2 * g + vc8h;
#pragma unroll
            for (int ks = 0; ks < 4; ks++) {
                uint32_t vf[4];
                const int rowV = 16 * ks + rVl;
                const uint32_t voff = (uint32_t)(cv * 8 + (rowV >> 3)) * 128
                                    + (((rowV & 7) ^ cv) * 16);
                ldm4t(vf, Vs + voff);
                mma16816h(oacc[2 * g],     pa[ks], vf);
                mma16816h(oacc[2 * g + 1], pa[ks], vf + 2);
            }
        }
    }

    l0 += __shfl_xor_sync(0xFFFFFFFFu, l0, 1);
    l0 += __shfl_xor_sync(0xFFFFFFFFu, l0, 2);
    l1 += __shfl_xor_sync(0xFFFFFFFFu, l1, 1);
    l1 += __shfl_xor_sync(0xFFFFFFFFu, l1, 2);
    const float iv0 = 1.0f / l0, iv1 = 1.0f / l1;
    const size_t gr0 = (rbase + row0) * C_;
    const size_t gr1 = (rbase + row1) * C_;
#pragma unroll
    for (int j = 0; j < 8; j++) {
        int col = h * DH_ + j * 8 + (lane & 3) * 2;
        *(uint32_t*)(oh + gr0 + col) = pack_h2(oacc[j][0] * iv0, oacc[j][1] * iv0);
        *(uint32_t*)(oh + gr1 + col) = pack_h2(oacc[j][2] * iv1, oacc[j][3] * iv1);
    }
}

// ---------------------------------------------------------------------------
extern "C" void kernel_launch(void* const* d_in, const int* in_sizes, int n_in,
                              void* d_out, int out_size)
{
    const float* x     = (const float*)d_in[0];
    const float* w_qkv = (const float*)d_in[1];
    const float* w_o   = (const float*)d_in[2];
    float* out = (float*)d_out;

    __half *xh, *qkvh, *wqh, *woh;
    cudaGetSymbolAddress((void**)&xh,   g_xh);
    cudaGetSymbolAddress((void**)&qkvh, g_qkvh);
    cudaGetSymbolAddress((void**)&wqh,  g_wqh);
    cudaGetSymbolAddress((void**)&woh,  g_woh);

    cudaFuncSetAttribute(gemm_mma, cudaFuncAttributeMaxDynamicSharedMemorySize, GEMM_SMEM);
    cudaFuncSetAttribute(attn_mma, cudaFuncAttributeMaxDynamicSharedMemorySize, ATT_SMEM);

    // 0) fp16 conversions
    to_h16<<<(M_ * C_ + 255) / 256, 256>>>(x, xh, M_ * C_);
    transT_h16<<<dim3(C3_ / 32, C_ / 32), dim3(32, 8)>>>(w_qkv, wqh, C_, C3_);
    transT_h16<<<dim3(C_ / 32,  C_ / 32), dim3(32, 8)>>>(w_o,   woh, C_, C_);

    // 1) qkv = x @ w_qkv  (single product, fp16 out)
    gemm_mma<<<dim3(C3_ / 128, M_ / 128), 256, GEMM_SMEM>>>(
        xh, wqh, nullptr, qkvh, C3_);

    // 2) flash attention (single product, fp16x2 softmax); O -> xh (fp16)
    attn_mma<<<dim3(T_ / AQT, H_, B_), 256, ATT_SMEM>>>(qkvh, xh);

    // 3) out = O @ w_o (single product, fp32 out)
    gemm_mma<<<dim3(C_ / 128, M_ / 128), 256, GEMM_SMEM>>>(
        xh, woh, out, nullptr, C_);
}